// round 10
// baseline (speedup 1.0000x reference)
#include <cuda_runtime.h>

#define N_NODES 200000
#define N_SUPER 20000
#define N_EDGES 640000
#define EMB 256
#define NBLK 196   // ceil(N_NODES / 1024) scan blocks

// ---------------- scratch (static device globals; no allocs) ----------------
__device__ __align__(16) float g_proj[(size_t)N_SUPER * EMB];  // x1 rows of supernodes
__device__ __align__(16) int   g_rowmap[N_NODES];              // node -> supernode slot or -1
__device__ __align__(16) int   g_snode[N_SUPER];               // slot -> node id
__device__ __align__(16) int   g_cnt[N_NODES];                 // histogram, then scatter cursor
__device__ __align__(16) int   g_off[N_NODES + 1];             // CSR offsets (exclusive scan)
__device__ __align__(16) int   g_esrc[N_EDGES];                // encoded src: node id, or N_NODES+slot
__device__ int g_bsum[NBLK];
__device__ int g_bpre[NBLK];
__device__ int g_is64;

// ---------------- helpers ----------------
__device__ __forceinline__ int load_idx(const void* p, int i) {
    if (g_is64) return (int)((const long long*)p)[i];
    return ((const int*)p)[i];
}

__device__ __forceinline__ unsigned f2tf(float f) {
    unsigned u;
    asm("cvt.rna.tf32.f32 %0, %1;" : "=r"(u) : "f"(f));
    return u;
}

__device__ __forceinline__ void mma_tf32(float* c, const unsigned* a, const unsigned* b) {
    asm volatile("mma.sync.aligned.m16n8k8.row.col.f32.tf32.tf32.f32 "
                 "{%0,%1,%2,%3}, {%4,%5,%6,%7}, {%8,%9}, {%0,%1,%2,%3};"
                 : "+f"(c[0]), "+f"(c[1]), "+f"(c[2]), "+f"(c[3])
                 : "r"(a[0]), "r"(a[1]), "r"(a[2]), "r"(a[3]), "r"(b[0]), "r"(b[1]));
}

__device__ __forceinline__ const float4* row_ptr(int idx, const float* x) {
    return (idx < N_NODES) ? (const float4*)(x + (size_t)idx * EMB)
                           : (const float4*)(g_proj + (size_t)(idx - N_NODES) * EMB);
}

__device__ __forceinline__ void acc4(float4& a, const float4 v) {
    a.x += v.x; a.y += v.y; a.z += v.z; a.w += v.w;
}

// ---------------- dtype detection ----------------
__global__ void k_detect(const int* __restrict__ ei_words) {
    int all_zero = 1;
    for (int k = 0; k < 64; k++)
        if (ei_words[2 * k + 1] != 0) { all_zero = 0; break; }
    g_is64 = all_zero;
}

// ---------------- init ----------------
__global__ void k_init() {
    int i = blockIdx.x * blockDim.x + threadIdx.x;
    if (i < N_NODES) { g_rowmap[i] = -1; g_cnt[i] = 0; }
    if (i < N_SUPER) g_snode[i] = 0;
}

__global__ void k_set_rowmap(const void* __restrict__ sidx) {
    int s = blockIdx.x * blockDim.x + threadIdx.x;
    if (s < N_SUPER) {
        int v = load_idx(sidx, s);
        if (v >= 0 && v < N_NODES) { g_rowmap[v] = s; g_snode[s] = v; }
    }
}

// ---------------- CSR build: histogram -> scan -> scatter ----------------
__global__ void k_hist(const void* __restrict__ ei) {
    int e = blockIdx.x * blockDim.x + threadIdx.x;
    if (e >= N_EDGES) return;
    int dst = load_idx(ei, e);
    if (dst >= 0 && dst < N_NODES) atomicAdd(&g_cnt[dst], 1);
}

__global__ void k_scan1() {
    __shared__ int s[256];
    int b = blockIdx.x, t = threadIdx.x;
    int base = b * 1024 + t * 4;
    int v[4], sum = 0;
#pragma unroll
    for (int i = 0; i < 4; i++) {
        v[i] = (base + i < N_NODES) ? g_cnt[base + i] : 0;
        sum += v[i];
    }
    s[t] = sum;
    __syncthreads();
#pragma unroll
    for (int off = 1; off < 256; off <<= 1) {
        int add = (t >= off) ? s[t - off] : 0;
        __syncthreads();
        s[t] += add;
        __syncthreads();
    }
    int run = (t ? s[t - 1] : 0);
#pragma unroll
    for (int i = 0; i < 4; i++) {
        if (base + i < N_NODES) g_off[base + i] = run;
        run += v[i];
    }
    if (t == 255) g_bsum[b] = s[255];
}

__global__ void k_scan2() {
    __shared__ int s[256];
    int t = threadIdx.x;
    s[t] = (t < NBLK) ? g_bsum[t] : 0;
    __syncthreads();
#pragma unroll
    for (int off = 1; off < 256; off <<= 1) {
        int add = (t >= off) ? s[t - off] : 0;
        __syncthreads();
        s[t] += add;
        __syncthreads();
    }
    if (t < NBLK) g_bpre[t] = (t ? s[t - 1] : 0);
    if (t == 0) g_off[N_NODES] = s[NBLK - 1];
}

__global__ void k_scan3() {
    int i = blockIdx.x * blockDim.x + threadIdx.x;
    if (i < N_NODES) {
        g_off[i] += g_bpre[i >> 10];
        g_cnt[i] = 0;
    }
}

// scatter with supernode resolution baked in: store node id, or N_NODES+slot
__global__ void k_scatter(const void* __restrict__ ei) {
    int e = blockIdx.x * blockDim.x + threadIdx.x;
    if (e >= N_EDGES) return;
    int dst = load_idx(ei, e);
    int src = load_idx(ei, N_EDGES + e);
    if (dst < 0 || dst >= N_NODES || src < 0 || src >= N_NODES) return;
    int r = g_rowmap[src];
    int enc = (r >= 0) ? (N_NODES + r) : src;
    int pos = g_off[dst] + atomicAdd(&g_cnt[dst], 1);
    g_esrc[pos] = enc;
}

// ---------------- gemm1 (small): C = A @ W^T + bias + x[g_snode[row]] ----------------
#define BM 64
#define BN 256
#define BK 32
#define PAD 36

__global__ void __launch_bounds__(256, 2)
k_gemm_tf32(const float* __restrict__ A, const float* __restrict__ W,
            const float* __restrict__ bias, float* __restrict__ C, int M,
            const float* __restrict__ x)
{
    __shared__ unsigned As[BM * PAD];   // [m][k]
    __shared__ unsigned Bs[BN * PAD];   // [n][k]

    const int tid  = threadIdx.x;
    const int warp = tid >> 5, lane = tid & 31;
    const int wm   = warp >> 2, wn = warp & 3;     // 2 x 4 warp grid
    const int gid  = lane >> 2, tg = lane & 3;
    const int row0 = blockIdx.x * BM;

    float c[2][8][4];
#pragma unroll
    for (int mt = 0; mt < 2; mt++)
#pragma unroll
        for (int nt = 0; nt < 8; nt++)
#pragma unroll
            for (int q = 0; q < 4; q++) c[mt][nt][q] = 0.f;

    for (int k0 = 0; k0 < EMB; k0 += BK) {
#pragma unroll
        for (int t = 0; t < 2; t++) {
            int f = tid + t * 256;
            int m = f >> 3, kq = f & 7;
            int row = row0 + m;
            float4 v = make_float4(0.f, 0.f, 0.f, 0.f);
            if (row < M) v = *(const float4*)(A + (size_t)row * EMB + k0 + kq * 4);
            unsigned* p = &As[m * PAD + kq * 4];
            p[0] = f2tf(v.x); p[1] = f2tf(v.y); p[2] = f2tf(v.z); p[3] = f2tf(v.w);
        }
#pragma unroll
        for (int t = 0; t < 8; t++) {
            int f = tid + t * 256;
            int n = f >> 3, kq = f & 7;
            float4 v = *(const float4*)(W + (size_t)n * EMB + k0 + kq * 4);
            unsigned* p = &Bs[n * PAD + kq * 4];
            p[0] = f2tf(v.x); p[1] = f2tf(v.y); p[2] = f2tf(v.z); p[3] = f2tf(v.w);
        }
        __syncthreads();

#pragma unroll
        for (int ks = 0; ks < BK; ks += 8) {
            unsigned a[2][4], b[8][2];
#pragma unroll
            for (int mt = 0; mt < 2; mt++) {
                int mb = wm * 32 + mt * 16 + gid;
                a[mt][0] = As[mb * PAD + ks + tg];
                a[mt][1] = As[(mb + 8) * PAD + ks + tg];
                a[mt][2] = As[mb * PAD + ks + tg + 4];
                a[mt][3] = As[(mb + 8) * PAD + ks + tg + 4];
            }
#pragma unroll
            for (int nt = 0; nt < 8; nt++) {
                int nb = wn * 64 + nt * 8 + gid;
                b[nt][0] = Bs[nb * PAD + ks + tg];
                b[nt][1] = Bs[nb * PAD + ks + tg + 4];
            }
#pragma unroll
            for (int mt = 0; mt < 2; mt++)
#pragma unroll
                for (int nt = 0; nt < 8; nt++)
                    mma_tf32(c[mt][nt], a[mt], b[nt]);
        }
        __syncthreads();
    }

#pragma unroll
    for (int mt = 0; mt < 2; mt++) {
#pragma unroll
        for (int half = 0; half < 2; half++) {
            int row = row0 + wm * 32 + mt * 16 + gid + half * 8;
            if (row >= M) continue;
            const float* addrow = x + (size_t)g_snode[row] * EMB;   // projx = proj + x[snode]
#pragma unroll
            for (int nt = 0; nt < 8; nt++) {
                int col = wn * 64 + nt * 8 + 2 * tg;
                float v0 = c[mt][nt][half * 2 + 0] + bias[col];
                float v1 = c[mt][nt][half * 2 + 1] + bias[col + 1];
                float2 av = *(const float2*)(addrow + col);
                v0 += av.x; v1 += av.y;
                *(float2*)(C + (size_t)row * EMB + col) = make_float2(v0, v1);
            }
        }
    }
}

// ---------------- fused gather + GEMM:  out = x1 + (sum x1[src]) @ W2^T + deg*b2 -------
// Block owns 64 dst rows. Phase 1: warps register-accumulate CSR ranges, write A tile
// to smem as tf32. Phase 2: mainloop with A fully resident, B streamed per k-step.
#define APAD 260   // 256 + 4: same 4-bank row stride as PAD=36 layout (proven conflict-free)
#define BPAD 36
#define FUSED_SMEM ((64 * APAD + 256 * BPAD) * 4)   // 103,424 bytes

__global__ void __launch_bounds__(256, 2)
k_fused(const float* __restrict__ x, const float* __restrict__ W,
        const float* __restrict__ bias, float* __restrict__ out)
{
    extern __shared__ unsigned sm[];
    unsigned* As = sm;               // [64][APAD]
    unsigned* Bs = sm + 64 * APAD;   // [256][BPAD]

    const int tid  = threadIdx.x;
    const int warp = tid >> 5, lane = tid & 31;
    const int row0 = blockIdx.x * 64;

    // ---------------- phase 1: gather-accumulate 8 rows per warp ----------------
#pragma unroll 1
    for (int i = 0; i < 8; i++) {
        int m = warp * 8 + i;
        int d = row0 + m;
        int j   = g_off[d];
        int end = g_off[d + 1];
        float4 a0 = make_float4(0.f, 0.f, 0.f, 0.f);
        float4 a1 = make_float4(0.f, 0.f, 0.f, 0.f);

        for (; j + 4 <= end; j += 4) {
            int i0 = g_esrc[j], i1 = g_esrc[j + 1], i2 = g_esrc[j + 2], i3 = g_esrc[j + 3];
            const float4* p0 = row_ptr(i0, x);
            const float4* p1 = row_ptr(i1, x);
            const float4* p2 = row_ptr(i2, x);
            const float4* p3 = row_ptr(i3, x);
            float4 v00 = p0[lane], v01 = p0[lane + 32];
            float4 v10 = p1[lane], v11 = p1[lane + 32];
            float4 v20 = p2[lane], v21 = p2[lane + 32];
            float4 v30 = p3[lane], v31 = p3[lane + 32];
            acc4(a0, v00); acc4(a1, v01);
            acc4(a0, v10); acc4(a1, v11);
            acc4(a0, v20); acc4(a1, v21);
            acc4(a0, v30); acc4(a1, v31);
        }
        for (; j < end; j++) {
            const float4* p = row_ptr(g_esrc[j], x);
            acc4(a0, p[lane]); acc4(a1, p[lane + 32]);
        }
        // write tf32 A row: lane covers cols [4*lane..4*lane+3] and [128+4*lane..]
        uint4 q0 = make_uint4(f2tf(a0.x), f2tf(a0.y), f2tf(a0.z), f2tf(a0.w));
        uint4 q1 = make_uint4(f2tf(a1.x), f2tf(a1.y), f2tf(a1.z), f2tf(a1.w));
        *(uint4*)&As[m * APAD + 4 * lane]       = q0;
        *(uint4*)&As[m * APAD + 128 + 4 * lane] = q1;
    }
    __syncthreads();

    // ---------------- phase 2: GEMM mainloop (A resident) ----------------
    const int wm  = warp >> 2, wn = warp & 3;     // 2 x 4 warp grid
    const int gid = lane >> 2, tg = lane & 3;

    float c[2][8][4];
#pragma unroll
    for (int mt = 0; mt < 2; mt++)
#pragma unroll
        for (int nt = 0; nt < 8; nt++)
#pragma unroll
            for (int q = 0; q < 4; q++) c[mt][nt][q] = 0.f;

    for (int k0 = 0; k0 < EMB; k0 += BK) {
#pragma unroll
        for (int t = 0; t < 8; t++) {
            int f = tid + t * 256;
            int n = f >> 3, kq = f & 7;
            float4 v = *(const float4*)(W + (size_t)n * EMB + k0 + kq * 4);
            unsigned* p = &Bs[n * BPAD + kq * 4];
            p[0] = f2tf(v.x); p[1] = f2tf(v.y); p[2] = f2tf(v.z); p[3] = f2tf(v.w);
        }
        __syncthreads();

#pragma unroll
        for (int ks = 0; ks < BK; ks += 8) {
            unsigned a[2][4], b[8][2];
#pragma unroll
            for (int mt = 0; mt < 2; mt++) {
                int mb = wm * 32 + mt * 16 + gid;
                int kc = k0 + ks + tg;
                a[mt][0] = As[mb * APAD + kc];
                a[mt][1] = As[(mb + 8) * APAD + kc];
                a[mt][2] = As[mb * APAD + kc + 4];
                a[mt][3] = As[(mb + 8) * APAD + kc + 4];
            }
#pragma unroll
            for (int nt = 0; nt < 8; nt++) {
                int nb = wn * 64 + nt * 8 + gid;
                b[nt][0] = Bs[nb * BPAD + ks + tg];
                b[nt][1] = Bs[nb * BPAD + ks + tg + 4];
            }
#pragma unroll
            for (int mt = 0; mt < 2; mt++)
#pragma unroll
                for (int nt = 0; nt < 8; nt++)
                    mma_tf32(c[mt][nt], a[mt], b[nt]);
        }
        __syncthreads();
    }

    // ---------------- epilogue: out = acc + b2*deg + x1[row] ----------------
#pragma unroll
    for (int mt = 0; mt < 2; mt++) {
#pragma unroll
        for (int half = 0; half < 2; half++) {
            int row = row0 + wm * 32 + mt * 16 + gid + half * 8;
            float dg = (float)(g_off[row + 1] - g_off[row]);
            int r = g_rowmap[row];
            const float* addrow = (r >= 0) ? (g_proj + (size_t)r * EMB)
                                           : (x + (size_t)row * EMB);
#pragma unroll
            for (int nt = 0; nt < 8; nt++) {
                int col = wn * 64 + nt * 8 + 2 * tg;
                float v0 = c[mt][nt][half * 2 + 0] + bias[col]     * dg;
                float v1 = c[mt][nt][half * 2 + 1] + bias[col + 1] * dg;
                float2 av = *(const float2*)(addrow + col);
                v0 += av.x; v1 += av.y;
                *(float2*)(out + (size_t)row * EMB + col) = make_float2(v0, v1);
            }
        }
    }
}

// ---------------- launch ----------------
extern "C" void kernel_launch(void* const* d_in, const int* in_sizes, int n_in,
                              void* d_out, int out_size) {
    const float *x = nullptr, *snx = nullptr;
    const float *W1 = nullptr, *b1 = nullptr, *W2 = nullptr, *b2 = nullptr;
    const void  *ei = nullptr, *sidx = nullptr;

    for (int i = 0; i < n_in; i++) {
        int s = in_sizes[i];
        if      (s == N_NODES * EMB)  x    = (const float*)d_in[i];
        else if (s == N_SUPER * EMB)  snx  = (const float*)d_in[i];
        else if (s == 2 * N_EDGES)    ei   = d_in[i];
        else if (s == N_SUPER)        sidx = d_in[i];
        else if (s == N_NODES)        { /* graph_batch, unused */ }
        else if (s == EMB * EMB) { if (!W1) W1 = (const float*)d_in[i]; else W2 = (const float*)d_in[i]; }
        else if (s == EMB)       { if (!b1) b1 = (const float*)d_in[i]; else b2 = (const float*)d_in[i]; }
    }
    float* out = (float*)d_out;

    void* p_proj;
    cudaGetSymbolAddress(&p_proj, g_proj);

    static int smem_set = 0;
    if (!smem_set) {
        cudaFuncSetAttribute(k_fused, cudaFuncAttributeMaxDynamicSharedMemorySize,
                             FUSED_SMEM);
        smem_set = 1;
    }

    // detection + init + CSR build
    k_detect<<<1, 1>>>((const int*)ei);
    k_init<<<(N_NODES + 255) / 256, 256>>>();
    k_set_rowmap<<<(N_SUPER + 255) / 256, 256>>>(sidx);
    k_hist<<<(N_EDGES + 255) / 256, 256>>>(ei);
    k_scan1<<<NBLK, 256>>>();
    k_scan2<<<1, 256>>>();
    k_scan3<<<(N_NODES + 255) / 256, 256>>>();
    k_scatter<<<(N_EDGES + 255) / 256, 256>>>(ei);

    // step 1: projx = x[sidx] + snx @ W1^T + b1  (supernode x1 rows)
    k_gemm_tf32<<<(N_SUPER + BM - 1) / BM, 256>>>(snx, W1, b1, (float*)p_proj,
                                                  N_SUPER, x);

    // step 2 (fused): out = x1 + (sum_{src->row} x1[src]) @ W2^T + deg * b2
    k_fused<<<N_NODES / 64, 256, FUSED_SMEM>>>(x, W2, b2, out);
}